// round 12
// baseline (speedup 1.0000x reference)
#include <cuda_runtime.h>
#include <cuda_bf16.h>
#include <math.h>

#define A_   128
#define D_   128
#define DM1  127
#define MAXB 64
#define VP   36          // v_sh quarter pitch (floats) — bank-swizzle
#define NSTEP 64         // 63 fused pair-steps + 1 tail step

// Fused transition matrices, bf16, packed for the forward kernel.
// Slot s (0..125): pair p = s>>1, variant x = s&1 : M_p[x] = T_2p diag(e_{2p+1,x}) T_{2p+1}
// Slot 126: plain T[126] (tail step).
// Packing (uint4 units): u4 = ((slot*16 + w)*4 + c)*32 + lane, lane's uint4 c
// holds k = 32*(lane>>3) + 8c + r (r=0..7), j = 8w + (lane&7).
__device__ uint4  g_M4[(size_t)127 * 2048];
// fp32 softmax of u_log_transition (scratch for the fuse GEMMs): [d][k][j].
__device__ float  g_Tf[(size_t)DM1 * A_ * A_];
// Emission table: {sigmoid(l), sigmoid(-l)} = {p(x=1), p(x=0)} per (d,j).
__device__ float2 g_S2[D_ * A_];
// Initial-state probabilities.
__device__ float  g_pa1[A_];

// ---------------------------------------------------------------------------
// f32x2 packed-FMA helpers (sm_103a FFMA2 — only reachable via PTX).
// ---------------------------------------------------------------------------
#define PACK_F32X2(out, lo, hi) \
    asm("mov.b64 %0, {%1, %2};" : "=l"(out) : "f"(lo), "f"(hi))
#define UNPACK_F32X2(lo, hi, in) \
    asm("mov.b64 {%0, %1}, %2;" : "=f"(lo), "=f"(hi) : "l"(in))
#define FMA_F32X2(acc, a, b) \
    asm("fma.rn.f32x2 %0, %1, %2, %0;" : "+l"(acc) : "l"(a), "l"(b))

// ---------------------------------------------------------------------------
// Prep A: row softmax of u_log_transition -> g_Tf (fp32); slot 126 of g_M4
// gets T[126] packed directly. One warp per (d,k) row.
// ---------------------------------------------------------------------------
__global__ void k_prepT(const float* __restrict__ u) {
    int w = threadIdx.x >> 5, lane = threadIdx.x & 31;
    int row = blockIdx.x * 8 + w;
    if (row >= DM1 * A_) return;
    float4 v4 = reinterpret_cast<const float4*>(u)[(size_t)row * 32 + lane];
    float m = fmaxf(fmaxf(v4.x, v4.y), fmaxf(v4.z, v4.w));
    #pragma unroll
    for (int o = 16; o > 0; o >>= 1) m = fmaxf(m, __shfl_xor_sync(0xffffffffu, m, o));
    float e0 = __expf(v4.x - m), e1 = __expf(v4.y - m);
    float e2 = __expf(v4.z - m), e3 = __expf(v4.w - m);
    float s = e0 + e1 + e2 + e3;
    #pragma unroll
    for (int o = 16; o > 0; o >>= 1) s += __shfl_xor_sync(0xffffffffu, s, o);
    float inv = 1.0f / s;
    float pv[4] = {e0 * inv, e1 * inv, e2 * inv, e3 * inv};

    reinterpret_cast<float4*>(g_Tf)[(size_t)row * 32 + lane] =
        make_float4(pv[0], pv[1], pv[2], pv[3]);

    int d = row >> 7;
    if (d == 126) {                // pack tail matrix into g_M4 slot 126
        int k = row & (A_ - 1);
        int c = (k & 31) >> 3;
        int r = k & 7;
        int kq = k >> 5;
        __nv_bfloat16* tb = reinterpret_cast<__nv_bfloat16*>(g_M4);
        #pragma unroll
        for (int qq = 0; qq < 4; ++qq) {
            int j = 4 * lane + qq;
            size_t bidx = ((((size_t)126 * 16 + (j >> 3)) * 4 + c) * 32 +
                           ((j & 7) | (kq << 3))) * 8 + r;
            tb[bidx] = __float2bfloat16_rn(pv[qq]);
        }
    }
}

// ---------------------------------------------------------------------------
// Prep B: emission sigmoid table.
// ---------------------------------------------------------------------------
__global__ void k_prepS(const float* __restrict__ lpx) {
    int i = blockIdx.x * 256 + threadIdx.x;
    if (i < D_ * A_) {
        float l = lpx[i];
        g_S2[i] = make_float2(1.0f / (1.0f + __expf(-l)),
                              1.0f / (1.0f + __expf(l)));
    }
}

// ---------------------------------------------------------------------------
// Prep C: softmax of u_log_p_a1 -> g_pa1; writes log_p_a1 output tail.
// ---------------------------------------------------------------------------
__global__ void k_pa1(const float* __restrict__ u, float* __restrict__ out,
                      int base, int out_size) {
    __shared__ float sred[4];
    int t = threadIdx.x, lane = t & 31, w = t >> 5;
    float v = u[t];
    float m = v;
    #pragma unroll
    for (int o = 16; o > 0; o >>= 1) m = fmaxf(m, __shfl_xor_sync(0xffffffffu, m, o));
    if (lane == 0) sred[w] = m;
    __syncthreads();
    m = fmaxf(fmaxf(sred[0], sred[1]), fmaxf(sred[2], sred[3]));
    __syncthreads();
    float e = __expf(v - m);
    float s = e;
    #pragma unroll
    for (int o = 16; o > 0; o >>= 1) s += __shfl_xor_sync(0xffffffffu, s, o);
    if (lane == 0) sred[w] = s;
    __syncthreads();
    s = sred[0] + sred[1] + sred[2] + sred[3];
    float lp = v - m - logf(s);
    g_pa1[t] = __expf(lp);
    int idx = base + t;
    if (idx < out_size) out[idx] = lp;
}

// ---------------------------------------------------------------------------
// Fuse GEMM: slot = blockIdx.x (0..125), p = slot>>1, x = slot&1.
// C[i][j] = sum_k T2p[i][k] * e(2p+1,k,x) * T2p1[k][j], fp32, FFMA2 inner.
// Block 512 (16x32 threads of 4x8 tiles; 4 warps/SMSP for latency hiding).
// Output packed bf16 via smem staging.
// Dynamic smem: As[128][132] fp32 (transposed) | Bs[128][128] fp32 | Es[128].
// ---------------------------------------------------------------------------
#define AP 132
#define BS_OFF (128 * AP)
#define ES_OFF (BS_OFF + 128 * 128)
#define MM_SMEM ((ES_OFF + 128) * 4)

__global__ void __launch_bounds__(512, 1) k_matmul() {
    extern __shared__ float sm[];
    float* As = sm;
    float* Bs = sm + BS_OFF;
    float* Es = sm + ES_OFF;

    const int slot = blockIdx.x;
    const int p = slot >> 1, xv = slot & 1;
    const int tid = threadIdx.x;

    const float* Am = g_Tf + (size_t)(2 * p) * 16384;
    const float* Bm = g_Tf + (size_t)(2 * p + 1) * 16384;

    if (tid < 128) {
        float2 sv = g_S2[(2 * p + 1) * A_ + tid];
        Es[tid] = xv ? sv.x : sv.y;
    }
    __syncthreads();

    for (int idx = tid; idx < 16384; idx += 512) {
        int i = idx >> 7, k = idx & 127;
        As[k * AP + i] = Am[idx] * Es[k];
        Bs[idx] = Bm[idx];
    }
    __syncthreads();

    const int tx = tid & 15, ty = tid >> 4;    // ty in 0..31
    const int i0 = ty * 4, j0 = tx * 8;

    unsigned long long cc[4][4];
    #pragma unroll
    for (int mi = 0; mi < 4; ++mi)
        #pragma unroll
        for (int q = 0; q < 4; ++q) cc[mi][q] = 0ull;

    #pragma unroll 2
    for (int kk = 0; kk < 128; ++kk) {
        float4 aA = *reinterpret_cast<const float4*>(&As[kk * AP + i0]);
        const ulonglong2* bp =
            reinterpret_cast<const ulonglong2*>(&Bs[kk * 128 + j0]);
        ulonglong2 b01 = bp[0], b23 = bp[1];
        float am[4] = {aA.x, aA.y, aA.z, aA.w};
        #pragma unroll
        for (int mi = 0; mi < 4; ++mi) {
            unsigned long long aa;
            PACK_F32X2(aa, am[mi], am[mi]);
            FMA_F32X2(cc[mi][0], aa, b01.x);
            FMA_F32X2(cc[mi][1], aa, b01.y);
            FMA_F32X2(cc[mi][2], aa, b23.x);
            FMA_F32X2(cc[mi][3], aa, b23.y);
        }
    }
    __syncthreads();   // done reading As/Bs; reuse As region as bf16 staging

    __nv_bfloat16* stage = reinterpret_cast<__nv_bfloat16*>(sm);
    #pragma unroll
    for (int mi = 0; mi < 4; ++mi) {
        int i = i0 + mi;                      // k-role index in forward
        int lnhalf = (i >> 5) << 3;           // kq bits of lane
        int c = (i & 31) >> 3;
        int r = i & 7;
        #pragma unroll
        for (int q = 0; q < 4; ++q) {
            float lo, hi;
            UNPACK_F32X2(lo, hi, cc[mi][q]);
            int j = j0 + 2 * q;
            size_t li = ((((size_t)(j >> 3)) * 4 + c) * 32 +
                         ((j & 7) | lnhalf)) * 8 + r;
            stage[li] = __float2bfloat16_rn(lo);
            size_t li2 = ((((size_t)((j + 1) >> 3)) * 4 + c) * 32 +
                          (((j + 1) & 7) | lnhalf)) * 8 + r;
            stage[li2] = __float2bfloat16_rn(hi);
        }
    }
    __syncthreads();

    uint4* dst = g_M4 + (size_t)slot * 2048;
    const uint4* src = reinterpret_cast<const uint4*>(sm);
    for (int idx = tid; idx < 2048; idx += 512) dst[idx] = src[idx];
}

// ---------------------------------------------------------------------------
// Main forward recurrence over 64 fused steps. grid = B, block = 512.
// Warp w owns j in [8w,8w+8) over all k; lane l: j = 8w+(l&7),
// k-quarter = l>>3; ONE barrier per step.
// Matrix slot per step s: s<63 -> 2s + x[b,2s+1]; s=63 -> 126 (tail).
// Emission per step s: e_{2s+2} (s<63) else e_127. Rescale every 8 steps.
// ---------------------------------------------------------------------------
__global__ void __launch_bounds__(512, 1) k_forward(const float* __restrict__ x,
                                                    float* __restrict__ out,
                                                    int out_size) {
    const int b = blockIdx.x;
    const int t = threadIdx.x;
    const int w = t >> 5, lane = t & 31;
    const int jown = 8 * w + (lane & 7);
    const int kq = lane >> 3;
    const int vq = kq * VP;
    const bool writer = (lane < 8);

    __shared__ __align__(16) float v_sh[2][4 * VP];
    __shared__ float s_red[16];
    __shared__ float sx[D_];

    if (t < D_) sx[t] = x[b * D_ + t];
    __syncthreads();

    float e_pref, acc = 0.f;
    {
        float2 s0 = g_S2[jown];
        float v0 = ((sx[0] > 0.5f) ? s0.x : s0.y) * g_pa1[jown];
        if (writer) v_sh[0][(jown >> 5) * VP + (jown & 31)] = v0;
        float2 s2 = g_S2[2 * A_ + jown];       // e for step 0 = e_2
        e_pref = (sx[2] > 0.5f) ? s2.x : s2.y;
    }
    __syncthreads();   // v_sh[0] ready

#define SLOT(S) (((S) < 63) ? (2 * (S) + ((sx[2 * (S) + 1] > 0.5f) ? 1 : 0)) : 126)

    // per-(warp,lane) base in uint4 units; +slot*2048 per matrix; +c*32
    const uint4* Tb = g_M4 + (size_t)w * 128 + lane;

    uint4 TA[4], TB[4];
    {
        const uint4* tp = Tb + (size_t)SLOT(0) * 2048;
        #pragma unroll
        for (int c = 0; c < 4; ++c) TA[c] = tp[c * 32];
    }

    float vfin = 0.f;

#define PREFETCH_T(DST, SL) do {                                             \
        const uint4* _tp = Tb + (size_t)(SL) * 2048;                         \
        _Pragma("unroll")                                                    \
        for (int c = 0; c < 4; ++c) (DST)[c] = _tp[c * 32];                  \
    } while (0)

#define CHUNK(R, OFF, ACC) do {                                              \
        float4 va = *reinterpret_cast<const float4*>(&vr[(OFF)]);            \
        float4 vb = *reinterpret_cast<const float4*>(&vr[(OFF) + 4]);        \
        ACC = fmaf(__uint_as_float((R).x << 16),         va.x, ACC);         \
        ACC = fmaf(__uint_as_float((R).x & 0xffff0000u), va.y, ACC);         \
        ACC = fmaf(__uint_as_float((R).y << 16),         va.z, ACC);         \
        ACC = fmaf(__uint_as_float((R).y & 0xffff0000u), va.w, ACC);         \
        ACC = fmaf(__uint_as_float((R).z << 16),         vb.x, ACC);         \
        ACC = fmaf(__uint_as_float((R).z & 0xffff0000u), vb.y, ACC);         \
        ACC = fmaf(__uint_as_float((R).w << 16),         vb.z, ACC);         \
        ACC = fmaf(__uint_as_float((R).w & 0xffff0000u), vb.w, ACC);         \
    } while (0)

#define STEP(DD, TARR) do {                                                  \
        const int rb = (DD) & 1, wb = ((DD) + 1) & 1;                        \
        const float* vr = &v_sh[rb][vq];                                     \
        float acc0 = 0.f, acc1 = 0.f;                                        \
        CHUNK((TARR)[0], 0,  acc0);                                          \
        CHUNK((TARR)[1], 8,  acc1);                                          \
        CHUNK((TARR)[2], 16, acc0);                                          \
        CHUNK((TARR)[3], 24, acc1);                                          \
        float sum = acc0 + acc1;                                             \
        sum += __shfl_xor_sync(0xffffffffu, sum, 8);                         \
        sum += __shfl_xor_sync(0xffffffffu, sum, 16);                        \
        float val = sum * e_pref;                                            \
        if (writer) v_sh[wb][(jown >> 5) * VP + (jown & 31)] = val;          \
        vfin = val;                                                          \
        {   /* prefetch emission for next step */                            \
            int de = ((DD) + 1 < 63) ? (2 * (DD) + 4) : 127;                 \
            float2 sn = g_S2[de * A_ + jown];                                \
            e_pref = (sx[de] > 0.5f) ? sn.x : sn.y;                          \
        }                                                                    \
        const bool resc = (((DD) & 7) == 7) && ((DD) != 63);                 \
        if (resc) {                                                          \
            float m = val;                                                   \
            m = fmaxf(m, __shfl_xor_sync(0xffffffffu, m, 1));                \
            m = fmaxf(m, __shfl_xor_sync(0xffffffffu, m, 2));                \
            m = fmaxf(m, __shfl_xor_sync(0xffffffffu, m, 4));                \
            if (lane == 0) s_red[w] = m;                                     \
        }                                                                    \
        __syncthreads();   /* publishes v_sh[wb] (+ s_red on resc steps) */  \
        if (resc) {                                                          \
            float mm = fmaxf(                                                \
                fmaxf(fmaxf(s_red[0],  s_red[1]),  fmaxf(s_red[2],  s_red[3])),  \
                fmaxf(fmaxf(s_red[4],  s_red[5]),  fmaxf(s_red[6],  s_red[7]))); \
            mm = fmaxf(mm, fmaxf(                                            \
                fmaxf(fmaxf(s_red[8],  s_red[9]),  fmaxf(s_red[10], s_red[11])), \
                fmaxf(fmaxf(s_red[12], s_red[13]), fmaxf(s_red[14], s_red[15])))); \
            e_pref *= (1.0f / mm);                                           \
            acc += __logf(mm);                                               \
        }                                                                    \
    } while (0)

    for (int s = 0; s < NSTEP; s += 2) {
        PREFETCH_T(TB, SLOT(s + 1));
        STEP(s, TA);
        PREFETCH_T(TA, SLOT(s + 2));   // SLOT(64) -> 126, harmless
        STEP(s + 1, TB);
    }

#undef STEP
#undef CHUNK
#undef PREFETCH_T
#undef SLOT

    // final: log_px[b] = acc + log(sum_j v_final[j])
    float sv = vfin;
    sv += __shfl_xor_sync(0xffffffffu, sv, 1);
    sv += __shfl_xor_sync(0xffffffffu, sv, 2);
    sv += __shfl_xor_sync(0xffffffffu, sv, 4);
    if (lane == 0) s_red[w] = sv;
    __syncthreads();
    float tot = (((s_red[0]  + s_red[1])  + (s_red[2]  + s_red[3]))
              +  ((s_red[4]  + s_red[5])  + (s_red[6]  + s_red[7])))
              + (((s_red[8]  + s_red[9])  + (s_red[10] + s_red[11]))
              +  ((s_red[12] + s_red[13]) + (s_red[14] + s_red[15])));
    float res = acc + __logf(tot);
    if (writer) {
        int idx = b * A_ + jown;
        if (idx < out_size) out[idx] = res;
    }
}

// ---------------------------------------------------------------------------
extern "C" void kernel_launch(void* const* d_in, const int* in_sizes, int n_in,
                              void* d_out, int out_size) {
    const float* x     = (const float*)d_in[0];   // [B, D]
    const float* u_pa1 = (const float*)d_in[1];   // [1,1,1,A]
    const float* u_T   = (const float*)d_in[2];   // [D-1, A, A]
    const float* lpx   = (const float*)d_in[3];   // [1, D, 1, A]
    float* out = (float*)d_out;

    int B = in_sizes[0] / D_;
    if (B > MAXB) B = MAXB;

    static bool attr_set = false;
    if (!attr_set) {
        cudaFuncSetAttribute(k_matmul,
                             cudaFuncAttributeMaxDynamicSharedMemorySize,
                             MM_SMEM);
        attr_set = true;
    }

    k_prepT<<<(DM1 * A_ + 7) / 8, 256>>>(u_T);
    k_prepS<<<(D_ * A_ + 255) / 256, 256>>>(lpx);
    k_pa1<<<1, 128>>>(u_pa1, out, B * A_, out_size);
    k_matmul<<<126, 512, MM_SMEM>>>();
    k_forward<<<B, 512>>>(x, out, out_size);
}

// round 16
// speedup vs baseline: 1.0329x; 1.0329x over previous
#include <cuda_runtime.h>
#include <cuda_bf16.h>
#include <math.h>
#include <cstdint>

#define A_   128
#define D_   128
#define DM1  127
#define MAXB 64
#define VP   36          // v_sh quarter pitch (floats) — bank-swizzle
#define NSTEP 64         // 63 fused pair-steps + 1 tail step

// Fused transition matrices, bf16, packed for the forward kernel.
// Slot s (0..125): pair p = s>>1, variant x = s&1: M_p[x] = T_2p diag(e_{2p+1,x}) T_{2p+1}
// Slot 126: plain T[126] (tail step).
// Packing (uint4 units): u4 = ((slot*16 + w)*4 + c)*32 + lane; the uint4 holds
// 8 bf16 for k = 32*(lane>>3) + 8c + r (r=0..7), at j = 8w + (lane&7).
__device__ uint4  g_M4[(size_t)127 * 2048];
// fp32 softmax of u_log_transition (scratch for the fuse GEMMs): [d][k][j].
__device__ float  g_Tf[(size_t)DM1 * A_ * A_];
// Emission table: {sigmoid(l), sigmoid(-l)} = {p(x=1), p(x=0)} per (d,j).
__device__ float2 g_S2[D_ * A_];
// Initial-state probabilities.
__device__ float  g_pa1[A_];

// ---------------------------------------------------------------------------
// Prep A: row softmax of u_log_transition -> g_Tf (fp32); slot 126 of g_M4
// gets T[126] packed directly. One warp per (d,k) row.
// ---------------------------------------------------------------------------
__global__ void k_prepT(const float* __restrict__ u) {
    int w = threadIdx.x >> 5, lane = threadIdx.x & 31;
    int row = blockIdx.x * 8 + w;
    if (row >= DM1 * A_) return;
    float4 v4 = reinterpret_cast<const float4*>(u)[(size_t)row * 32 + lane];
    float m = fmaxf(fmaxf(v4.x, v4.y), fmaxf(v4.z, v4.w));
    #pragma unroll
    for (int o = 16; o > 0; o >>= 1) m = fmaxf(m, __shfl_xor_sync(0xffffffffu, m, o));
    float e0 = __expf(v4.x - m), e1 = __expf(v4.y - m);
    float e2 = __expf(v4.z - m), e3 = __expf(v4.w - m);
    float s = e0 + e1 + e2 + e3;
    #pragma unroll
    for (int o = 16; o > 0; o >>= 1) s += __shfl_xor_sync(0xffffffffu, s, o);
    float inv = 1.0f / s;
    float pv[4] = {e0 * inv, e1 * inv, e2 * inv, e3 * inv};

    reinterpret_cast<float4*>(g_Tf)[(size_t)row * 32 + lane] =
        make_float4(pv[0], pv[1], pv[2], pv[3]);

    int d = row >> 7;
    if (d == 126) {                // pack tail matrix into g_M4 slot 126
        int k = row & (A_ - 1);
        int c = (k & 31) >> 3;
        int r = k & 7;
        int kq = k >> 5;
        __nv_bfloat16* tb = reinterpret_cast<__nv_bfloat16*>(g_M4);
        #pragma unroll
        for (int qq = 0; qq < 4; ++qq) {
            int j = 4 * lane + qq;
            size_t bidx = ((((size_t)126 * 16 + (j >> 3)) * 4 + c) * 32 +
                           ((j & 7) | (kq << 3))) * 8 + r;
            tb[bidx] = __float2bfloat16_rn(pv[qq]);
        }
    }
}

// ---------------------------------------------------------------------------
// Prep B: emission sigmoid table.
// ---------------------------------------------------------------------------
__global__ void k_prepS(const float* __restrict__ lpx) {
    int i = blockIdx.x * 256 + threadIdx.x;
    if (i < D_ * A_) {
        float l = lpx[i];
        g_S2[i] = make_float2(1.0f / (1.0f + __expf(-l)),
                              1.0f / (1.0f + __expf(l)));
    }
}

// ---------------------------------------------------------------------------
// Prep C: softmax of u_log_p_a1 -> g_pa1; writes log_p_a1 output tail.
// ---------------------------------------------------------------------------
__global__ void k_pa1(const float* __restrict__ u, float* __restrict__ out,
                      int base, int out_size) {
    __shared__ float sred[4];
    int t = threadIdx.x, lane = t & 31, w = t >> 5;
    float v = u[t];
    float m = v;
    #pragma unroll
    for (int o = 16; o > 0; o >>= 1) m = fmaxf(m, __shfl_xor_sync(0xffffffffu, m, o));
    if (lane == 0) sred[w] = m;
    __syncthreads();
    m = fmaxf(fmaxf(sred[0], sred[1]), fmaxf(sred[2], sred[3]));
    __syncthreads();
    float e = __expf(v - m);
    float s = e;
    #pragma unroll
    for (int o = 16; o > 0; o >>= 1) s += __shfl_xor_sync(0xffffffffu, s, o);
    if (lane == 0) sred[w] = s;
    __syncthreads();
    s = sred[0] + sred[1] + sred[2] + sred[3];
    float lp = v - m - logf(s);
    g_pa1[t] = __expf(lp);
    int idx = base + t;
    if (idx < out_size) out[idx] = lp;
}

// ---------------------------------------------------------------------------
// Fuse GEMM, plain fp32 FFMA. slot = blockIdx.x (0..125), p = slot>>1,
// x = slot&1. C[i][j] = sum_k T2p[i][k]*e_k*T2p1[k][j].
// Block 256 (16x16 threads of 8x8 tiles), fp32 accumulators (64 regs).
// Output packed bf16 via smem staging (reuses As region).
// Dynamic smem: As[128][132] fp32 (transposed) | Bs[128][128] fp32 | Es[128].
// ---------------------------------------------------------------------------
#define AP 132
#define BS_OFF (128 * AP)
#define ES_OFF (BS_OFF + 128 * 128)
#define MM_SMEM ((ES_OFF + 128) * 4)

__global__ void __launch_bounds__(256, 1) k_matmul() {
    extern __shared__ float sm[];
    float* As = sm;
    float* Bs = sm + BS_OFF;
    float* Es = sm + ES_OFF;

    const int slot = blockIdx.x;
    const int p = slot >> 1, xv = slot & 1;
    const int tid = threadIdx.x;

    const float* Am = g_Tf + (size_t)(2 * p) * 16384;
    const float* Bm = g_Tf + (size_t)(2 * p + 1) * 16384;

    if (tid < 128) {
        float2 sv = g_S2[(2 * p + 1) * A_ + tid];
        Es[tid] = xv ? sv.x : sv.y;
    }
    __syncthreads();

    for (int idx = tid; idx < 16384; idx += 256) {
        int i = idx >> 7, k = idx & 127;
        As[k * AP + i] = Am[idx] * Es[k];   // transposed: As[k][i]
        Bs[idx] = Bm[idx];                  // Bs[k][j]
    }
    __syncthreads();

    const int tx = tid & 15, ty = tid >> 4;
    const int i0 = ty * 8, j0 = tx * 8;

    float cc[8][8];
    #pragma unroll
    for (int mi = 0; mi < 8; ++mi)
        #pragma unroll
        for (int q = 0; q < 8; ++q) cc[mi][q] = 0.f;

    for (int kk = 0; kk < 128; ++kk) {
        float4 aA = *reinterpret_cast<const float4*>(&As[kk * AP + i0]);
        float4 aB = *reinterpret_cast<const float4*>(&As[kk * AP + i0 + 4]);
        float4 b0 = *reinterpret_cast<const float4*>(&Bs[kk * 128 + j0]);
        float4 b1 = *reinterpret_cast<const float4*>(&Bs[kk * 128 + j0 + 4]);
        float am[8] = {aA.x, aA.y, aA.z, aA.w, aB.x, aB.y, aB.z, aB.w};
        float bm[8] = {b0.x, b0.y, b0.z, b0.w, b1.x, b1.y, b1.z, b1.w};
        #pragma unroll
        for (int mi = 0; mi < 8; ++mi) {
            #pragma unroll
            for (int q = 0; q < 8; ++q)
                cc[mi][q] = fmaf(am[mi], bm[q], cc[mi][q]);
        }
    }
    __syncthreads();   // done reading As/Bs; reuse As region as bf16 staging

    __nv_bfloat16* stage = reinterpret_cast<__nv_bfloat16*>(sm);
    #pragma unroll
    for (int mi = 0; mi < 8; ++mi) {
        int i = i0 + mi;                      // k-role index in forward
        int lnhalf = (i >> 5) << 3;           // kq bits of lane
        int c = (i & 31) >> 3;
        int r = i & 7;
        #pragma unroll
        for (int q = 0; q < 8; ++q) {
            int j = j0 + q;
            size_t li = ((((size_t)(j >> 3)) * 4 + c) * 32 +
                         ((j & 7) | lnhalf)) * 8 + r;
            stage[li] = __float2bfloat16_rn(cc[mi][q]);
        }
    }
    __syncthreads();

    uint4* dst = g_M4 + (size_t)slot * 2048;
    const uint4* src = reinterpret_cast<const uint4*>(sm);
    for (int idx = tid; idx < 2048; idx += 256) dst[idx] = src[idx];
}

// ---------------------------------------------------------------------------
// Main forward recurrence over 64 fused steps. grid = B, block = 512.
// Warp w owns j in [8w,8w+8) over all k; lane l: j = 8w+(l&7),
// k-quarter = l>>3; ONE barrier per step.
// Matrix slot per step s: s<63 -> 2s + x[b,2s+1]; s=63 -> 126 (tail).
// Emission per step s: e_{2s+2} (s<63) else e_127. Rescale every 8 steps.
// ---------------------------------------------------------------------------
__global__ void __launch_bounds__(512, 1) k_forward(const float* __restrict__ x,
                                                    float* __restrict__ out,
                                                    int out_size) {
    const int b = blockIdx.x;
    const int t = threadIdx.x;
    const int w = t >> 5, lane = t & 31;
    const int jown = 8 * w + (lane & 7);
    const int kq = lane >> 3;
    const int vq = kq * VP;
    const bool writer = (lane < 8);

    __shared__ __align__(16) float v_sh[2][4 * VP];
    __shared__ float s_red[16];
    __shared__ float sx[D_];

    if (t < D_) sx[t] = x[b * D_ + t];
    __syncthreads();

    float e_pref, acc = 0.f;
    {
        float2 s0 = g_S2[jown];
        float v0 = ((sx[0] > 0.5f) ? s0.x : s0.y) * g_pa1[jown];
        if (writer) v_sh[0][(jown >> 5) * VP + (jown & 31)] = v0;
        float2 s2 = g_S2[2 * A_ + jown];       // e for step 0 = e_2
        e_pref = (sx[2] > 0.5f) ? s2.x : s2.y;
    }
    __syncthreads();   // v_sh[0] ready

#define SLOT(S) (((S) < 63) ? (2 * (S) + ((sx[2 * (S) + 1] > 0.5f) ? 1 : 0)) : 126)

    const uint4* Tb = g_M4 + (size_t)w * 128 + lane;

    uint4 TA[4], TB[4];
    {
        const uint4* tp = Tb + (size_t)SLOT(0) * 2048;
        #pragma unroll
        for (int c = 0; c < 4; ++c) TA[c] = tp[c * 32];
    }

    float vfin = 0.f;

#define PREFETCH_T(DST, SL) do {                                             \
        const uint4* _tp = Tb + (size_t)(SL) * 2048;                         \
        _Pragma("unroll")                                                    \
        for (int c = 0; c < 4; ++c) (DST)[c] = _tp[c * 32];                  \
    } while (0)

#define CHUNK(R, OFF, ACC) do {                                              \
        float4 va = *reinterpret_cast<const float4*>(&vr[(OFF)]);            \
        float4 vb = *reinterpret_cast<const float4*>(&vr[(OFF) + 4]);        \
        ACC = fmaf(__uint_as_float((R).x << 16),         va.x, ACC);         \
        ACC = fmaf(__uint_as_float((R).x & 0xffff0000u), va.y, ACC);         \
        ACC = fmaf(__uint_as_float((R).y << 16),         va.z, ACC);         \
        ACC = fmaf(__uint_as_float((R).y & 0xffff0000u), va.w, ACC);         \
        ACC = fmaf(__uint_as_float((R).z << 16),         vb.x, ACC);         \
        ACC = fmaf(__uint_as_float((R).z & 0xffff0000u), vb.y, ACC);         \
        ACC = fmaf(__uint_as_float((R).w << 16),         vb.z, ACC);         \
        ACC = fmaf(__uint_as_float((R).w & 0xffff0000u), vb.w, ACC);         \
    } while (0)

#define STEP(DD, TARR) do {                                                  \
        const int rb = (DD) & 1, wb = ((DD) + 1) & 1;                        \
        const float* vr = &v_sh[rb][vq];                                     \
        float acc0 = 0.f, acc1 = 0.f;                                        \
        CHUNK((TARR)[0], 0,  acc0);                                          \
        CHUNK((TARR)[1], 8,  acc1);                                          \
        CHUNK((TARR)[2], 16, acc0);                                          \
        CHUNK((TARR)[3], 24, acc1);                                          \
        float sum = acc0 + acc1;                                             \
        sum += __shfl_xor_sync(0xffffffffu, sum, 8);                         \
        sum += __shfl_xor_sync(0xffffffffu, sum, 16);                        \
        float val = sum * e_pref;                                            \
        if (writer) v_sh[wb][(jown >> 5) * VP + (jown & 31)] = val;          \
        vfin = val;                                                          \
        {   /* prefetch emission for next step */                            \
            int de = ((DD) + 1 < 63) ? (2 * (DD) + 4) : 127;                 \
            float2 sn = g_S2[de * A_ + jown];                                \
            e_pref = (sx[de] > 0.5f) ? sn.x : sn.y;                          \
        }                                                                    \
        const bool resc = (((DD) & 7) == 7) && ((DD) != 63);                 \
        if (resc) {                                                          \
            float m = val;                                                   \
            m = fmaxf(m, __shfl_xor_sync(0xffffffffu, m, 1));                \
            m = fmaxf(m, __shfl_xor_sync(0xffffffffu, m, 2));                \
            m = fmaxf(m, __shfl_xor_sync(0xffffffffu, m, 4));                \
            if (lane == 0) s_red[w] = m;                                     \
        }                                                                    \
        __syncthreads();   /* publishes v_sh[wb] (+ s_red on resc steps) */  \
        if (resc) {                                                          \
            float mm = fmaxf(                                                \
                fmaxf(fmaxf(s_red[0],  s_red[1]),  fmaxf(s_red[2],  s_red[3])),  \
                fmaxf(fmaxf(s_red[4],  s_red[5]),  fmaxf(s_red[6],  s_red[7]))); \
            mm = fmaxf(mm, fmaxf(                                            \
                fmaxf(fmaxf(s_red[8],  s_red[9]),  fmaxf(s_red[10], s_red[11])), \
                fmaxf(fmaxf(s_red[12], s_red[13]), fmaxf(s_red[14], s_red[15])))); \
            e_pref *= (1.0f / mm);                                           \
            acc += __logf(mm);                                               \
        }                                                                    \
    } while (0)

    for (int s = 0; s < NSTEP; s += 2) {
        PREFETCH_T(TB, SLOT(s + 1));
        STEP(s, TA);
        PREFETCH_T(TA, SLOT(s + 2));   // SLOT(64) -> 126, harmless
        STEP(s + 1, TB);
    }

#undef STEP
#undef CHUNK
#undef PREFETCH_T
#undef SLOT

    // final: log_px[b] = acc + log(sum_j v_final[j])
    float sv = vfin;
    sv += __shfl_xor_sync(0xffffffffu, sv, 1);
    sv += __shfl_xor_sync(0xffffffffu, sv, 2);
    sv += __shfl_xor_sync(0xffffffffu, sv, 4);
    if (lane == 0) s_red[w] = sv;
    __syncthreads();
    float tot = (((s_red[0]  + s_red[1])  + (s_red[2]  + s_red[3]))
              +  ((s_red[4]  + s_red[5])  + (s_red[6]  + s_red[7])))
              + (((s_red[8]  + s_red[9])  + (s_red[10] + s_red[11]))
              +  ((s_red[12] + s_red[13]) + (s_red[14] + s_red[15])));
    float res = acc + __logf(tot);
    if (writer) {
        int idx = b * A_ + jown;
        if (idx < out_size) out[idx] = res;
    }
}

// ---------------------------------------------------------------------------
extern "C" void kernel_launch(void* const* d_in, const int* in_sizes, int n_in,
                              void* d_out, int out_size) {
    const float* x     = (const float*)d_in[0];   // [B, D]
    const float* u_pa1 = (const float*)d_in[1];   // [1,1,1,A]
    const float* u_T   = (const float*)d_in[2];   // [D-1, A, A]
    const float* lpx   = (const float*)d_in[3];   // [1, D, 1, A]
    float* out = (float*)d_out;

    int B = in_sizes[0] / D_;
    if (B > MAXB) B = MAXB;

    static bool attr_set = false;
    if (!attr_set) {
        cudaFuncSetAttribute(k_matmul,
                             cudaFuncAttributeMaxDynamicSharedMemorySize,
                             MM_SMEM);
        attr_set = true;
    }

    k_prepT<<<(DM1 * A_ + 7) / 8, 256>>>(u_T);
    k_prepS<<<(D_ * A_ + 255) / 256, 256>>>(lpx);
    k_pa1<<<1, 128>>>(u_pa1, out, B * A_, out_size);
    k_matmul<<<126, 256, MM_SMEM>>>();
    k_forward<<<B, 512>>>(x, out, out_size);
}